// round 14
// baseline (speedup 1.0000x reference)
#include <cuda_runtime.h>
#include <math.h>
#include <stdint.h>

// Problem constants
#define Bq   2
#define Sq   2048
#define Dq   512
#define Hq   8
#define Kq   16
#define DHq  64
#define EPSq 1e-8f
#define BS   4096
#define BH   16
#define ACH  32     // kv token chunks of 128 (16 per batch)

// ---------------- tiny device scratch (~1.1 MB total) ----------------
__device__ float g_Mpart[ACH * Hq * Kq * DHq];  // 1 MB
__device__ float g_sspart[ACH * Hq * Kq];       // 16 KB
__device__ float g_M[BH * Kq * DHq];            // 64 KB
__device__ float g_ss[BH * Kq];                 // 1 KB

__device__ __forceinline__ float warpSum(float p) {
    p += __shfl_xor_sync(0xffffffffu, p, 16);
    p += __shfl_xor_sync(0xffffffffu, p, 8);
    p += __shfl_xor_sync(0xffffffffu, p, 4);
    p += __shfl_xor_sync(0xffffffffu, p, 2);
    p += __shfl_xor_sync(0xffffffffu, p, 1);
    return p;
}

// ---------------- packed f32x2 helpers (C1/C2) ----------------
typedef unsigned long long u64t;
__device__ __forceinline__ u64t pack2(float lo, float hi) {
    u64t r; asm("mov.b64 %0, {%1, %2};" : "=l"(r) : "f"(lo), "f"(hi)); return r;
}
__device__ __forceinline__ u64t packrep(float v) { return pack2(v, v); }
__device__ __forceinline__ void fma2(u64t& c, u64t a, u64t b) {
    asm("fma.rn.f32x2 %0, %1, %2, %0;" : "+l"(c) : "l"(a), "l"(b));
}
__device__ __forceinline__ float2 unpk(u64t v) {
    float2 f; asm("mov.b64 {%0, %1}, %2;" : "=f"(f.x), "=f"(f.y) : "l"(v)); return f;
}

// ---------------- tf32 split helpers ----------------
__device__ __forceinline__ void cvt_split(float v, uint32_t& h, uint32_t& l) {
    asm("cvt.rna.tf32.f32 %0, %1;" : "=r"(h) : "f"(v));
    float hf = __uint_as_float(h);
    float lo = v - hf;                      // exact residual
    asm("cvt.rna.tf32.f32 %0, %1;" : "=r"(l) : "f"(lo));
}

#define MMA_TF32(c, a0_, a1_, a2_, a3_, b0_, b1_) \
    asm volatile("mma.sync.aligned.m16n8k8.row.col.f32.tf32.tf32.f32 " \
                 "{%0,%1,%2,%3}, {%4,%5,%6,%7}, {%8,%9}, {%0,%1,%2,%3};" \
                 : "+f"((c)[0]), "+f"((c)[1]), "+f"((c)[2]), "+f"((c)[3]) \
                 : "r"(a0_), "r"(a1_), "r"(a2_), "r"(a3_), \
                   "r"(b0_), "r"(b1_))

// smem plan for kernel A (floats / u32):
//   GEMM phase: Ah[128][36]=4608, Al=4608, Bh[32][136]=4352, Bl=4352 -> 17920
//   splat phase (OVERLAY on GEMM region): ks[128][68]=8704, vs=8704 -> 17408
//   persistent: sp[16][65]=1040, sinv=16  at offset 17920
#define A_SMEM_FLOATS (17920 + 1040 + 16)
#define A_SMEM_BYTES  (A_SMEM_FLOATS * 4)                       // 75904
// C2: qs[16][512]=8192, Ws[16][512]=8192, sp 1024, sM 1024, consts 48
#define C2_SMEM_FLOATS (8192 + 8192 + 1024 + 1024 + 48)
#define C2_SMEM_BYTES  (C2_SMEM_FLOATS * 4)                     // 73920

// ============================================================================
// Kernel A: fused K/V projection via tf32 MMA (3-term split) + splat moments.
// grid (32, 8) = 256 blocks, 256 threads (8 warps, 2x4), 74 KB smem, 2 blk/SM.
// ============================================================================
__global__ __launch_bounds__(256, 2) void kv_splat_kernel(
    const float* __restrict__ x,  const float* __restrict__ Wk,
    const float* __restrict__ Wv, const float* __restrict__ lscale,
    const float* __restrict__ pos)
{
    if (x == nullptr) return;   // warm-up guard
    extern __shared__ float sm[];
    uint32_t* Ah = (uint32_t*)sm;            // [128][36]
    uint32_t* Al = Ah + 4608;
    uint32_t* Bh = Ah + 9216;                // [32][136]
    uint32_t* Bl = Ah + 13568;               // ends at 17920
    float* ks   = sm;                        // OVERLAY: [128][68]
    float* vs   = sm + 8704;                 //          ends 17408 (<17920)
    float* sp   = sm + 17920;                // [16][65]
    float* sinv = sm + 18960;                // [16]

    const int chunk = blockIdx.x;            // token rows chunk*128
    const int h     = blockIdx.y;
    const int rowBase = chunk * 128;
    const int tid  = threadIdx.x;
    const int lane = tid & 31, warp = tid >> 5;
    const int warpY = warp >> 2;             // 0..1 -> 64 rows
    const int warpX = warp & 3;              // 0..3 -> 32 cols
    const int g = lane >> 2, tig = lane & 3;

    // splat constants
#pragma unroll
    for (int i = 0; i < 4; i++) {
        int idx = tid + i * 256;             // 0..1023
        int r = idx >> 6, d = idx & 63;
        sp[r * 65 + d] = pos[h * 1024 + r * 64 + d];
    }
    if (tid < 16) {
        float sc = __expf(lscale[h * 16 + tid]);
        sc = fminf(fmaxf(sc, 0.1f), 2.0f);
        sinv[tid] = 1.0f / (2.0f * sc * sc);
    }

    float acc[4][4][4];
#pragma unroll
    for (int mt = 0; mt < 4; mt++)
#pragma unroll
        for (int nt = 0; nt < 4; nt++)
#pragma unroll
            for (int j = 0; j < 4; j++) acc[mt][nt][j] = 0.0f;

    for (int kc = 0; kc < 512; kc += 32) {
        // x tile -> Ah/Al [row][36]
#pragma unroll
        for (int i = 0; i < 16; i++) {
            int idx = tid + i * 256;         // 0..4095
            int row = idx >> 5, kk = idx & 31;
            float v = x[(size_t)(rowBase + row) * 512 + kc + kk];
            uint32_t hb, lb; cvt_split(v, hb, lb);
            Ah[row * 36 + kk] = hb;
            Al[row * 36 + kk] = lb;
        }
        // W tile -> Bh/Bl [kk][136]
#pragma unroll
        for (int i = 0; i < 16; i++) {
            int idx = tid + i * 256;
            int kk = idx >> 7, col = idx & 127;
            float v = (col < 64)
                ? Wk[(size_t)(kc + kk) * 512 + h * 64 + col]
                : Wv[(size_t)(kc + kk) * 512 + h * 64 + col - 64];
            uint32_t hb, lb; cvt_split(v, hb, lb);
            Bh[kk * 136 + col] = hb;
            Bl[kk * 136 + col] = lb;
        }
        __syncthreads();

#pragma unroll
        for (int s8 = 0; s8 < 4; s8++) {
            const int kb = s8 * 8;
            uint32_t bh[4][2], bl[4][2];
#pragma unroll
            for (int nt = 0; nt < 4; nt++) {
                int c0 = warpX * 32 + nt * 8 + g;
                bh[nt][0] = Bh[(kb + tig) * 136 + c0];
                bh[nt][1] = Bh[(kb + tig + 4) * 136 + c0];
                bl[nt][0] = Bl[(kb + tig) * 136 + c0];
                bl[nt][1] = Bl[(kb + tig + 4) * 136 + c0];
            }
#pragma unroll
            for (int mt = 0; mt < 4; mt++) {
                int r0 = warpY * 64 + mt * 16;
                int i0 = (r0 + g) * 36 + kb + tig;
                int i1 = i0 + 8 * 36;
                uint32_t a0 = Ah[i0],     a1 = Ah[i1];
                uint32_t a2 = Ah[i0 + 4], a3 = Ah[i1 + 4];
                uint32_t l0 = Al[i0],     l1 = Al[i1];
                uint32_t l2 = Al[i0 + 4], l3 = Al[i1 + 4];
#pragma unroll
                for (int nt = 0; nt < 4; nt++) {
                    MMA_TF32(acc[mt][nt], a0, a1, a2, a3, bh[nt][0], bh[nt][1]);
                    MMA_TF32(acc[mt][nt], a0, a1, a2, a3, bl[nt][0], bl[nt][1]);
                    MMA_TF32(acc[mt][nt], l0, l1, l2, l3, bh[nt][0], bh[nt][1]);
                }
            }
        }
        __syncthreads();
    }

    // writeout accumulators onto OVERLAY ks/vs (cols 0..63 K, 64..127 V)
    {
        float* cb = (warpX < 2) ? ks : vs;
#pragma unroll
        for (int mt = 0; mt < 4; mt++) {
            int r = warpY * 64 + mt * 16 + g;
#pragma unroll
            for (int nt = 0; nt < 4; nt++) {
                int c = (warpX & 1) * 32 + nt * 8 + tig * 2;
                cb[r * 68 + c]           = acc[mt][nt][0];
                cb[r * 68 + c + 1]       = acc[mt][nt][1];
                cb[(r + 8) * 68 + c]     = acc[mt][nt][2];
                cb[(r + 8) * 68 + c + 1] = acc[mt][nt][3];
            }
        }
    }
    __syncthreads();

    // ---- splat moment accumulation: 8 warps, warp handles splats w and w+8 ----
    const float p0a = sp[warp * 65 + lane],       p1a = sp[warp * 65 + lane + 32];
    const float p0b = sp[(warp + 8) * 65 + lane], p1b = sp[(warp + 8) * 65 + lane + 32];
    const float inva = sinv[warp], invb = sinv[warp + 8];

    float mA0 = 0.f, mA1 = 0.f, sA = 0.f;
    float mB0 = 0.f, mB1 = 0.f, sB = 0.f;
#pragma unroll 2
    for (int tt = 0; tt < 128; tt++) {
        float k0v = ks[tt * 68 + lane], k1v = ks[tt * 68 + lane + 32];
        float v0  = vs[tt * 68 + lane], v1  = vs[tt * 68 + lane + 32];
        float d0 = k0v - p0a, d1 = k1v - p1a;
        float dd = warpSum(d0 * d0 + d1 * d1);
        float af = __expf(-dd * inva);
        mA0 = fmaf(af, v0, mA0); mA1 = fmaf(af, v1, mA1); sA += af;
        d0 = k0v - p0b; d1 = k1v - p1b;
        dd = warpSum(d0 * d0 + d1 * d1);
        af = __expf(-dd * invb);
        mB0 = fmaf(af, v0, mB0); mB1 = fmaf(af, v1, mB1); sB += af;
    }
    const size_t base = ((size_t)chunk * Hq + h) * Kq;
    float* Mp  = &g_Mpart[(base + warp) * DHq];
    Mp[lane] = mA0; Mp[lane + 32] = mA1;
    float* Mp2 = &g_Mpart[(base + warp + 8) * DHq];
    Mp2[lane] = mB0; Mp2[lane + 32] = mB1;
    if (lane == 0) {
        g_sspart[base + warp]     = sA;
        g_sspart[base + warp + 8] = sB;
    }
}

// ============================================================================
// Kernel B: fixed-order reduction of chunk partials (deterministic).
// ============================================================================
__global__ __launch_bounds__(256) void reduce_kernel(int real)
{
    if (!real) return;   // warm-up guard
    const int i = blockIdx.x * 256 + threadIdx.x;
    if (i < BH * Kq * DHq) {            // 16384
        int bh = i >> 10;
        int b = bh >> 3, h = bh & 7;
        int rest = i & 1023;
        float a = 0.f;
#pragma unroll
        for (int c = 0; c < 16; c++)
            a += g_Mpart[(((size_t)(b * 16 + c) * Hq + h) << 10) + rest];
        g_M[i] = a;
    }
    if (i < BH * Kq) {                  // 256
        int bh = i >> 4;
        int b = bh >> 3, h = bh & 7;
        int k = i & 15;
        float a = 0.f;
#pragma unroll
        for (int c = 0; c < 16; c++)
            a += g_sspart[((size_t)(b * 16 + c) * Hq + h) * Kq + k];
        g_ss[i] = a;
    }
}

// ============================================================================
// Kernel C1: q = x @ Wq -> d_out staging (scalar fp32 + f32x2, unchanged).
// ============================================================================
__global__ __launch_bounds__(256) void q_proj_kernel(
    const float* __restrict__ x, const float* __restrict__ Wq, float* __restrict__ C)
{
    if (x == nullptr) return;   // warm-up guard
    __shared__ float As[16 * 64];
    __shared__ float Bs[16 * 132];

    const int tid = threadIdx.x;
    const int tx = tid & 15, ty = tid >> 4;
    const int rowBase = blockIdx.y * 64;
    const int colBase = blockIdx.x * 128;

#define DECLR(r) u64t c##r##0 = 0, c##r##1 = 0, c##r##2 = 0, c##r##3 = 0;
    DECLR(0) DECLR(1) DECLR(2) DECLR(3)
#undef DECLR

    for (int k0 = 0; k0 < Dq; k0 += 16) {
        {
            int arow = tid >> 2, acg = tid & 3;
            float4 a = *(const float4*)&x[(size_t)(rowBase + arow) * Dq + k0 + acg * 4];
            As[(acg * 4 + 0) * 64 + arow] = a.x;
            As[(acg * 4 + 1) * 64 + arow] = a.y;
            As[(acg * 4 + 2) * 64 + arow] = a.z;
            As[(acg * 4 + 3) * 64 + arow] = a.w;
        }
#pragma unroll
        for (int ld = 0; ld < 2; ld++) {
            int f = tid + ld * 256;
            int brow = f >> 5, bcg = f & 31;
            float4 b = *(const float4*)&Wq[(size_t)(k0 + brow) * Dq + colBase + bcg * 4];
            Bs[brow * 132 + bcg * 4 + 0] = b.x;
            Bs[brow * 132 + bcg * 4 + 1] = b.y;
            Bs[brow * 132 + bcg * 4 + 2] = b.z;
            Bs[brow * 132 + bcg * 4 + 3] = b.w;
        }
        __syncthreads();
#pragma unroll
        for (int kk = 0; kk < 16; kk++) {
            float4 a  = *(const float4*)&As[kk * 64 + ty * 4];
            ulonglong2 bb0 = *(const ulonglong2*)&Bs[kk * 132 + tx * 8];
            ulonglong2 bb1 = *(const ulonglong2*)&Bs[kk * 132 + tx * 8 + 4];
            u64t b0 = bb0.x, b1 = bb0.y, b2 = bb1.x, b3 = bb1.y;
#define RSTEP(r, s) { u64t ap = packrep(s); fma2(c##r##0, ap, b0); fma2(c##r##1, ap, b1); \
                      fma2(c##r##2, ap, b2); fma2(c##r##3, ap, b3); }
            RSTEP(0, a.x) RSTEP(1, a.y) RSTEP(2, a.z) RSTEP(3, a.w)
#undef RSTEP
        }
        __syncthreads();
    }

#define C1ST(r) { ulonglong2* p = (ulonglong2*)&C[(size_t)(rowBase + ty * 4 + (r)) * Dq + colBase + tx * 8]; \
                  p[0] = make_ulonglong2(c##r##0, c##r##1); \
                  p[1] = make_ulonglong2(c##r##2, c##r##3); }
    C1ST(0) C1ST(1) C1ST(2) C1ST(3)
#undef C1ST
}

// ============================================================================
// Kernel C2: per 16-token block — splat all heads in-place + out = y @ Wo,
// written back to the SAME rows of d_out (row-disjoint -> in-place safe).
// grid 256 blocks x 256 threads, 72 KB smem -> 2 blocks/SM, all SMs.
// ============================================================================
__global__ __launch_bounds__(256, 2) void splat_out_kernel(
    float* __restrict__ io, const float* __restrict__ Wo,
    const float* __restrict__ lscale, const float* __restrict__ pos,
    const float* __restrict__ amp)
{
    if (Wo == nullptr) return;   // warm-up guard
    extern __shared__ float sm[];
    float* qs   = sm;               // [16][512]  (q, then y)
    float* Ws   = sm + 8192;        // [16][512]  Wo k-chunk
    float* sp   = Ws + 8192;        // [16][64]
    float* sM   = sp + 1024;        // [16][64]
    float* sinv = sM + 1024;
    float* samp = sinv + 16;
    float* sss  = samp + 16;

    const int tid = threadIdx.x;
    const int tokBase = blockIdx.x * 16;
    const int b = tokBase >> 11;
    const int warp = tid >> 5, lane = tid & 31;
    const int tg = tid >> 6, cg = tid & 63;

    // load q tile [16][512]
#pragma unroll
    for (int i = 0; i < 8; i++) {
        int f = tid + i * 256;
        int r = f >> 7, c4 = f & 127;
        *(float4*)&qs[r * 512 + c4 * 4] = *(const float4*)&io[(size_t)(tokBase + r) * Dq + c4 * 4];
    }
    __syncthreads();

    // splat per head, in place over qs (warp owns 2 tokens)
    for (int h = 0; h < Hq; h++) {
        {
            int r = tid >> 4, c4 = tid & 15;
            *(float4*)&sp[r * 64 + c4 * 4] = *(const float4*)&pos[(h * Kq + r) * DHq + c4 * 4];
            *(float4*)&sM[r * 64 + c4 * 4] = *(const float4*)&g_M[((size_t)(b * 8 + h) * Kq + r) * DHq + c4 * 4];
        }
        if (tid < Kq) {
            float sc = __expf(lscale[h * Kq + tid]);
            sc = fminf(fmaxf(sc, 0.1f), 2.0f);
            sinv[tid] = 1.0f / (2.0f * sc * sc);
            samp[tid] = amp[h * Kq + tid];
            sss[tid]  = g_ss[(b * 8 + h) * Kq + tid];
        }
        __syncthreads();
#pragma unroll
        for (int i = 0; i < 2; i++) {
            int tok = warp * 2 + i;
            float q0 = qs[tok * 512 + h * 64 + lane];
            float q1 = qs[tok * 512 + h * 64 + lane + 32];
            float den = 0.f, y0 = 0.f, y1 = 0.f;
#pragma unroll
            for (int k = 0; k < Kq; k++) {
                float d0 = q0 - sp[k * 64 + lane];
                float d1 = q1 - sp[k * 64 + lane + 32];
                float dd = warpSum(d0 * d0 + d1 * d1);
                float w  = __expf(-dd * sinv[k]) * samp[k];
                den = fmaf(w, sss[k], den);
                y0  = fmaf(w, sM[k * 64 + lane],      y0);
                y1  = fmaf(w, sM[k * 64 + lane + 32], y1);
            }
            float r = 1.0f / (den + EPSq);
            qs[tok * 512 + h * 64 + lane]      = y0 * r;
            qs[tok * 512 + h * 64 + lane + 32] = y1 * r;
        }
        __syncthreads();
    }

    // out GEMM: out[16,512] = y[16,512] @ Wo[512,512]; token-pairs as f32x2
    // thread: rows tg*4..tg*4+3 (2 pairs) x 8 strided cols -> 16 f32x2 accs
#define DECLO(p) u64t o##p##0 = 0, o##p##1 = 0, o##p##2 = 0, o##p##3 = 0, \
                      o##p##4 = 0, o##p##5 = 0, o##p##6 = 0, o##p##7 = 0;
    DECLO(0) DECLO(1)
#undef DECLO

    for (int k0 = 0; k0 < Dq; k0 += 16) {
#pragma unroll
        for (int i = 0; i < 8; i++) {
            int f = tid + i * 256;
            int r = f >> 7, c4 = f & 127;
            *(float4*)&Ws[r * 512 + c4 * 4] = *(const float4*)&Wo[(size_t)(k0 + r) * Dq + c4 * 4];
        }
        __syncthreads();
#pragma unroll 2
        for (int kk = 0; kk < 16; kk++) {
            u64t wp0 = packrep(Ws[kk * 512 + cg]);
            u64t wp1 = packrep(Ws[kk * 512 + cg + 64]);
            u64t wp2 = packrep(Ws[kk * 512 + cg + 128]);
            u64t wp3 = packrep(Ws[kk * 512 + cg + 192]);
            u64t wp4 = packrep(Ws[kk * 512 + cg + 256]);
            u64t wp5 = packrep(Ws[kk * 512 + cg + 320]);
            u64t wp6 = packrep(Ws[kk * 512 + cg + 384]);
            u64t wp7 = packrep(Ws[kk * 512 + cg + 448]);
            u64t yp0 = pack2(qs[(tg * 4 + 0) * 512 + k0 + kk], qs[(tg * 4 + 1) * 512 + k0 + kk]);
            u64t yp1 = pack2(qs[(tg * 4 + 2) * 512 + k0 + kk], qs[(tg * 4 + 3) * 512 + k0 + kk]);
#define C2FMA(p, yp) { fma2(o##p##0, yp, wp0); fma2(o##p##1, yp, wp1); fma2(o##p##2, yp, wp2); fma2(o##p##3, yp, wp3); \
                       fma2(o##p##4, yp, wp4); fma2(o##p##5, yp, wp5); fma2(o##p##6, yp, wp6); fma2(o##p##7, yp, wp7); }
            C2FMA(0, yp0) C2FMA(1, yp1)
#undef C2FMA
        }
        __syncthreads();
    }

#define C2OUT(p) { \
    float* r0 = &io[(size_t)(tokBase + tg * 4 + 2 * (p)) * Dq + cg]; \
    float* r1 = r0 + Dq; float2 f; \
    f = unpk(o##p##0); r0[0]   = f.x; r1[0]   = f.y; \
    f = unpk(o##p##1); r0[64]  = f.x; r1[64]  = f.y; \
    f = unpk(o##p##2); r0[128] = f.x; r1[128] = f.y; \
    f = unpk(o##p##3); r0[192] = f.x; r1[192] = f.y; \
    f = unpk(o##p##4); r0[256] = f.x; r1[256] = f.y; \
    f = unpk(o##p##5); r0[320] = f.x; r1[320] = f.y; \
    f = unpk(o##p##6); r0[384] = f.x; r1[384] = f.y; \
    f = unpk(o##p##7); r0[448] = f.x; r1[448] = f.y; }
    C2OUT(0) C2OUT(1)
#undef C2OUT
}

// ---------------- static-init warm-up + stream/event creation ----------------
namespace {
cudaStream_t g_side[16] = {};
cudaEvent_t  g_evF[16]  = {};
cudaEvent_t  g_evJ[16]  = {};

void warm_one_device() {
    (void)cudaFree(0);
    void* p = nullptr;
    (void)cudaGetSymbolAddress(&p, g_M);
    (void)cudaGetSymbolAddress(&p, g_Mpart);
    (void)cudaFuncSetAttribute(kv_splat_kernel,
            cudaFuncAttributeMaxDynamicSharedMemorySize, A_SMEM_BYTES);
    (void)cudaFuncSetAttribute(splat_out_kernel,
            cudaFuncAttributeMaxDynamicSharedMemorySize, C2_SMEM_BYTES);
    {
        dim3 grid(ACH, Hq);
        kv_splat_kernel<<<grid, 256, A_SMEM_BYTES>>>(nullptr, nullptr, nullptr, nullptr, nullptr);
    }
    reduce_kernel<<<64, 256>>>(0);
    {
        dim3 grid(4, 64);
        q_proj_kernel<<<grid, 256>>>(nullptr, nullptr, nullptr);
    }
    splat_out_kernel<<<256, 256, C2_SMEM_BYTES>>>(nullptr, nullptr, nullptr, nullptr, nullptr);
    (void)cudaDeviceSynchronize();
    int d = 0;
    if (cudaGetDevice(&d) == cudaSuccess && d >= 0 && d < 16 && g_side[d] == nullptr) {
        if (cudaStreamCreateWithFlags(&g_side[d], cudaStreamNonBlocking) != cudaSuccess)
            g_side[d] = nullptr;
        if (g_side[d]) {
            if (cudaEventCreateWithFlags(&g_evF[d], cudaEventDisableTiming) != cudaSuccess) g_evF[d] = nullptr;
            if (cudaEventCreateWithFlags(&g_evJ[d], cudaEventDisableTiming) != cudaSuccess) g_evJ[d] = nullptr;
        }
    }
    (void)cudaGetLastError();
}
struct ModuleWarmup {
    ModuleWarmup() {
        int prev = 0;
        (void)cudaGetDevice(&prev);
        int n = 0;
        if (cudaGetDeviceCount(&n) != cudaSuccess) n = 0;
        for (int d = 0; d < n && d < 16; d++) {
            if (cudaSetDevice(d) != cudaSuccess) continue;
            warm_one_device();
        }
        (void)cudaSetDevice(prev);
        (void)cudaGetLastError();
    }
};
ModuleWarmup s_warmup;
}

// ---------------- launch ----------------
extern "C" void kernel_launch(void* const* d_in, const int* in_sizes, int n_in,
                              void* d_out, int out_size)
{
    const float* x      = (const float*)d_in[0];
    const float* Wqm    = (const float*)d_in[1];
    const float* Wkm    = (const float*)d_in[2];
    const float* Wvm    = (const float*)d_in[3];
    const float* Wom    = (const float*)d_in[4];
    const float* pos    = (const float*)d_in[5];
    const float* lscale = (const float*)d_in[6];
    const float* amp    = (const float*)d_in[7];
    float* out = (float*)d_out;

    (void)cudaFuncSetAttribute(kv_splat_kernel,
            cudaFuncAttributeMaxDynamicSharedMemorySize, A_SMEM_BYTES);
    (void)cudaFuncSetAttribute(splat_out_kernel,
            cudaFuncAttributeMaxDynamicSharedMemorySize, C2_SMEM_BYTES);

    int dev = 0;
    (void)cudaGetDevice(&dev);
    cudaStream_t side = (dev >= 0 && dev < 16) ? g_side[dev] : nullptr;
    cudaEvent_t evF = (dev >= 0 && dev < 16) ? g_evF[dev] : nullptr;
    cudaEvent_t evJ = (dev >= 0 && dev < 16) ? g_evJ[dev] : nullptr;
    const bool overlap = (side != nullptr) && (evF != nullptr) && (evJ != nullptr);

    if (overlap) {
        // fork: C1 on side stream, concurrent with A + reduce on main stream
        cudaEventRecord(evF, 0);
        cudaStreamWaitEvent(side, evF, 0);
        {
            dim3 grid(4, 64);
            q_proj_kernel<<<grid, 256, 0, side>>>(x, Wqm, out);
        }
        cudaEventRecord(evJ, side);
    }

    {   // K/V projection (tf32 MMA) + splat moments
        dim3 grid(ACH, Hq);
        kv_splat_kernel<<<grid, 256, A_SMEM_BYTES>>>(x, Wkm, Wvm, lscale, pos);
    }
    reduce_kernel<<<64, 256>>>(1);

    if (overlap) {
        cudaStreamWaitEvent(0, evJ, 0);   // join C1 into main stream
    } else {
        dim3 grid(4, 64);
        q_proj_kernel<<<grid, 256>>>(x, Wqm, out);
    }

    // splat attention + output projection, in-place on d_out rows
    splat_out_kernel<<<256, 256, C2_SMEM_BYTES>>>(out, Wom, lscale, pos, amp);
}

// round 16
// speedup vs baseline: 1.2004x; 1.2004x over previous
#include <cuda_runtime.h>
#include <math.h>
#include <stdint.h>

// Problem constants
#define Bq   2
#define Sq   2048
#define Dq   512
#define Hq   8
#define Kq   16
#define DHq  64
#define EPSq 1e-8f
#define BS   4096
#define BH   16
#define ACH  32     // kv token chunks of 128 (16 per batch)

// ---------------- tiny device scratch (~1.1 MB total) ----------------
__device__ float g_Mpart[ACH * Hq * Kq * DHq];  // 1 MB
__device__ float g_sspart[ACH * Hq * Kq];       // 16 KB
__device__ float g_M[BH * Kq * DHq];            // 64 KB
__device__ float g_ss[BH * Kq];                 // 1 KB

__device__ __forceinline__ float warpSum(float p) {
    p += __shfl_xor_sync(0xffffffffu, p, 16);
    p += __shfl_xor_sync(0xffffffffu, p, 8);
    p += __shfl_xor_sync(0xffffffffu, p, 4);
    p += __shfl_xor_sync(0xffffffffu, p, 2);
    p += __shfl_xor_sync(0xffffffffu, p, 1);
    return p;
}

// ---------------- packed f32x2 helpers (C2) ----------------
typedef unsigned long long u64t;
__device__ __forceinline__ u64t pack2(float lo, float hi) {
    u64t r; asm("mov.b64 %0, {%1, %2};" : "=l"(r) : "f"(lo), "f"(hi)); return r;
}
__device__ __forceinline__ u64t packrep(float v) { return pack2(v, v); }
__device__ __forceinline__ void fma2(u64t& c, u64t a, u64t b) {
    asm("fma.rn.f32x2 %0, %1, %2, %0;" : "+l"(c) : "l"(a), "l"(b));
}
__device__ __forceinline__ float2 unpk(u64t v) {
    float2 f; asm("mov.b64 {%0, %1}, %2;" : "=f"(f.x), "=f"(f.y) : "l"(v)); return f;
}

// ---------------- tf32 split helpers ----------------
__device__ __forceinline__ void cvt_split(float v, uint32_t& h, uint32_t& l) {
    asm("cvt.rna.tf32.f32 %0, %1;" : "=r"(h) : "f"(v));
    float hf = __uint_as_float(h);
    float lo = v - hf;                      // exact residual
    asm("cvt.rna.tf32.f32 %0, %1;" : "=r"(l) : "f"(lo));
}

#define MMA_TF32(c, a0_, a1_, a2_, a3_, b0_, b1_) \
    asm volatile("mma.sync.aligned.m16n8k8.row.col.f32.tf32.tf32.f32 " \
                 "{%0,%1,%2,%3}, {%4,%5,%6,%7}, {%8,%9}, {%0,%1,%2,%3};" \
                 : "+f"((c)[0]), "+f"((c)[1]), "+f"((c)[2]), "+f"((c)[3]) \
                 : "r"(a0_), "r"(a1_), "r"(a2_), "r"(a3_), \
                   "r"(b0_), "r"(b1_))

// smem plans
// A: GEMM phase Ah[128][36]=4608,Al=4608,Bh[32][136]=4352,Bl=4352 -> 17920
//    splat OVERLAY ks[128][68]=8704, vs=8704 -> 17408 ; persistent sp/sinv at 17920
#define A_SMEM_FLOATS (17920 + 1040 + 16)
#define A_SMEM_BYTES  (A_SMEM_FLOATS * 4)                       // 75904
// C1 (tensor): Ah/Al/Bh/Bl only
#define C1_SMEM_FLOATS 17920
#define C1_SMEM_BYTES  (C1_SMEM_FLOATS * 4)                     // 71680
// C2 (R13 geometry): qs[32][512] + Ws[32][512] + sp + sM + consts
#define C2_SMEM_FLOATS (16384 + 16384 + 1024 + 1024 + 48)
#define C2_SMEM_BYTES  (C2_SMEM_FLOATS * 4)                     // 139456

// ============================================================================
// Kernel A: fused K/V projection via tf32 MMA (3-term split) + splat moments.
// grid (32, 8) = 256 blocks, 256 threads (8 warps, 2x4), 74 KB smem, 2 blk/SM.
// ============================================================================
__global__ __launch_bounds__(256, 2) void kv_splat_kernel(
    const float* __restrict__ x,  const float* __restrict__ Wk,
    const float* __restrict__ Wv, const float* __restrict__ lscale,
    const float* __restrict__ pos)
{
    if (x == nullptr) return;   // warm-up guard
    extern __shared__ float sm[];
    uint32_t* Ah = (uint32_t*)sm;            // [128][36]
    uint32_t* Al = Ah + 4608;
    uint32_t* Bh = Ah + 9216;                // [32][136]
    uint32_t* Bl = Ah + 13568;               // ends at 17920
    float* ks   = sm;                        // OVERLAY: [128][68]
    float* vs   = sm + 8704;                 //          ends 17408 (<17920)
    float* sp   = sm + 17920;                // [16][65]
    float* sinv = sm + 18960;                // [16]

    const int chunk = blockIdx.x;            // token rows chunk*128
    const int h     = blockIdx.y;
    const int rowBase = chunk * 128;
    const int tid  = threadIdx.x;
    const int lane = tid & 31, warp = tid >> 5;
    const int warpY = warp >> 2;             // 0..1 -> 64 rows
    const int warpX = warp & 3;              // 0..3 -> 32 cols
    const int g = lane >> 2, tig = lane & 3;

    // splat constants
#pragma unroll
    for (int i = 0; i < 4; i++) {
        int idx = tid + i * 256;             // 0..1023
        int r = idx >> 6, d = idx & 63;
        sp[r * 65 + d] = pos[h * 1024 + r * 64 + d];
    }
    if (tid < 16) {
        float sc = __expf(lscale[h * 16 + tid]);
        sc = fminf(fmaxf(sc, 0.1f), 2.0f);
        sinv[tid] = 1.0f / (2.0f * sc * sc);
    }

    float acc[4][4][4];
#pragma unroll
    for (int mt = 0; mt < 4; mt++)
#pragma unroll
        for (int nt = 0; nt < 4; nt++)
#pragma unroll
            for (int j = 0; j < 4; j++) acc[mt][nt][j] = 0.0f;

    for (int kc = 0; kc < 512; kc += 32) {
#pragma unroll
        for (int i = 0; i < 16; i++) {
            int idx = tid + i * 256;         // 0..4095
            int row = idx >> 5, kk = idx & 31;
            float v = x[(size_t)(rowBase + row) * 512 + kc + kk];
            uint32_t hb, lb; cvt_split(v, hb, lb);
            Ah[row * 36 + kk] = hb;
            Al[row * 36 + kk] = lb;
        }
#pragma unroll
        for (int i = 0; i < 16; i++) {
            int idx = tid + i * 256;
            int kk = idx >> 7, col = idx & 127;
            float v = (col < 64)
                ? Wk[(size_t)(kc + kk) * 512 + h * 64 + col]
                : Wv[(size_t)(kc + kk) * 512 + h * 64 + col - 64];
            uint32_t hb, lb; cvt_split(v, hb, lb);
            Bh[kk * 136 + col] = hb;
            Bl[kk * 136 + col] = lb;
        }
        __syncthreads();

#pragma unroll
        for (int s8 = 0; s8 < 4; s8++) {
            const int kb = s8 * 8;
            uint32_t bh[4][2], bl[4][2];
#pragma unroll
            for (int nt = 0; nt < 4; nt++) {
                int c0 = warpX * 32 + nt * 8 + g;
                bh[nt][0] = Bh[(kb + tig) * 136 + c0];
                bh[nt][1] = Bh[(kb + tig + 4) * 136 + c0];
                bl[nt][0] = Bl[(kb + tig) * 136 + c0];
                bl[nt][1] = Bl[(kb + tig + 4) * 136 + c0];
            }
#pragma unroll
            for (int mt = 0; mt < 4; mt++) {
                int r0 = warpY * 64 + mt * 16;
                int i0 = (r0 + g) * 36 + kb + tig;
                int i1 = i0 + 8 * 36;
                uint32_t a0 = Ah[i0],     a1 = Ah[i1];
                uint32_t a2 = Ah[i0 + 4], a3 = Ah[i1 + 4];
                uint32_t l0 = Al[i0],     l1 = Al[i1];
                uint32_t l2 = Al[i0 + 4], l3 = Al[i1 + 4];
#pragma unroll
                for (int nt = 0; nt < 4; nt++) {
                    MMA_TF32(acc[mt][nt], a0, a1, a2, a3, bh[nt][0], bh[nt][1]);
                    MMA_TF32(acc[mt][nt], a0, a1, a2, a3, bl[nt][0], bl[nt][1]);
                    MMA_TF32(acc[mt][nt], l0, l1, l2, l3, bh[nt][0], bh[nt][1]);
                }
            }
        }
        __syncthreads();
    }

    // writeout accumulators onto OVERLAY ks/vs (cols 0..63 K, 64..127 V)
    {
        float* cb = (warpX < 2) ? ks : vs;
#pragma unroll
        for (int mt = 0; mt < 4; mt++) {
            int r = warpY * 64 + mt * 16 + g;
#pragma unroll
            for (int nt = 0; nt < 4; nt++) {
                int c = (warpX & 1) * 32 + nt * 8 + tig * 2;
                cb[r * 68 + c]           = acc[mt][nt][0];
                cb[r * 68 + c + 1]       = acc[mt][nt][1];
                cb[(r + 8) * 68 + c]     = acc[mt][nt][2];
                cb[(r + 8) * 68 + c + 1] = acc[mt][nt][3];
            }
        }
    }
    __syncthreads();

    // ---- splat moment accumulation: 8 warps, warp handles splats w and w+8 ----
    const float p0a = sp[warp * 65 + lane],       p1a = sp[warp * 65 + lane + 32];
    const float p0b = sp[(warp + 8) * 65 + lane], p1b = sp[(warp + 8) * 65 + lane + 32];
    const float inva = sinv[warp], invb = sinv[warp + 8];

    float mA0 = 0.f, mA1 = 0.f, sA = 0.f;
    float mB0 = 0.f, mB1 = 0.f, sB = 0.f;
#pragma unroll 2
    for (int tt = 0; tt < 128; tt++) {
        float k0v = ks[tt * 68 + lane], k1v = ks[tt * 68 + lane + 32];
        float v0  = vs[tt * 68 + lane], v1  = vs[tt * 68 + lane + 32];
        float d0 = k0v - p0a, d1 = k1v - p1a;
        float dd = warpSum(d0 * d0 + d1 * d1);
        float af = __expf(-dd * inva);
        mA0 = fmaf(af, v0, mA0); mA1 = fmaf(af, v1, mA1); sA += af;
        d0 = k0v - p0b; d1 = k1v - p1b;
        dd = warpSum(d0 * d0 + d1 * d1);
        af = __expf(-dd * invb);
        mB0 = fmaf(af, v0, mB0); mB1 = fmaf(af, v1, mB1); sB += af;
    }
    const size_t base = ((size_t)chunk * Hq + h) * Kq;
    float* Mp  = &g_Mpart[(base + warp) * DHq];
    Mp[lane] = mA0; Mp[lane + 32] = mA1;
    float* Mp2 = &g_Mpart[(base + warp + 8) * DHq];
    Mp2[lane] = mB0; Mp2[lane + 32] = mB1;
    if (lane == 0) {
        g_sspart[base + warp]     = sA;
        g_sspart[base + warp + 8] = sB;
    }
}

// ============================================================================
// Kernel B: fixed-order reduction of chunk partials (deterministic).
// ============================================================================
__global__ __launch_bounds__(256) void reduce_kernel(int real)
{
    if (!real) return;   // warm-up guard
    const int i = blockIdx.x * 256 + threadIdx.x;
    if (i < BH * Kq * DHq) {            // 16384
        int bh = i >> 10;
        int b = bh >> 3, h = bh & 7;
        int rest = i & 1023;
        float a = 0.f;
#pragma unroll
        for (int c = 0; c < 16; c++)
            a += g_Mpart[(((size_t)(b * 16 + c) * Hq + h) << 10) + rest];
        g_M[i] = a;
    }
    if (i < BH * Kq) {                  // 256
        int bh = i >> 4;
        int b = bh >> 3, h = bh & 7;
        int k = i & 15;
        float a = 0.f;
#pragma unroll
        for (int c = 0; c < 16; c++)
            a += g_sspart[((size_t)(b * 16 + c) * Hq + h) * Kq + k];
        g_ss[i] = a;
    }
}

// ============================================================================
// Kernel C1: q = x @ Wq via tf32 MMA (3-term split) -> d_out staging.
// Same tile machinery as kernel A (validated mapping), full 128-col B tiles.
// grid (4, 32) = 128 blocks, 256 threads, 70 KB smem, 2 blk/SM.
// ============================================================================
__global__ __launch_bounds__(256, 2) void q_proj_kernel(
    const float* __restrict__ x, const float* __restrict__ Wq, float* __restrict__ C)
{
    if (x == nullptr) return;   // warm-up guard
    extern __shared__ float sm[];
    uint32_t* Ah = (uint32_t*)sm;            // [128][36]
    uint32_t* Al = Ah + 4608;
    uint32_t* Bh = Ah + 9216;                // [32][136]
    uint32_t* Bl = Ah + 13568;

    const int rowBase = blockIdx.y * 128;
    const int colBase = blockIdx.x * 128;
    const int tid  = threadIdx.x;
    const int lane = tid & 31, warp = tid >> 5;
    const int warpY = warp >> 2;
    const int warpX = warp & 3;
    const int g = lane >> 2, tig = lane & 3;

    float acc[4][4][4];
#pragma unroll
    for (int mt = 0; mt < 4; mt++)
#pragma unroll
        for (int nt = 0; nt < 4; nt++)
#pragma unroll
            for (int j = 0; j < 4; j++) acc[mt][nt][j] = 0.0f;

    for (int kc = 0; kc < 512; kc += 32) {
#pragma unroll
        for (int i = 0; i < 16; i++) {
            int idx = tid + i * 256;
            int row = idx >> 5, kk = idx & 31;
            float v = x[(size_t)(rowBase + row) * 512 + kc + kk];
            uint32_t hb, lb; cvt_split(v, hb, lb);
            Ah[row * 36 + kk] = hb;
            Al[row * 36 + kk] = lb;
        }
#pragma unroll
        for (int i = 0; i < 16; i++) {
            int idx = tid + i * 256;
            int kk = idx >> 7, col = idx & 127;
            float v = Wq[(size_t)(kc + kk) * 512 + colBase + col];
            uint32_t hb, lb; cvt_split(v, hb, lb);
            Bh[kk * 136 + col] = hb;
            Bl[kk * 136 + col] = lb;
        }
        __syncthreads();

#pragma unroll
        for (int s8 = 0; s8 < 4; s8++) {
            const int kb = s8 * 8;
            uint32_t bh[4][2], bl[4][2];
#pragma unroll
            for (int nt = 0; nt < 4; nt++) {
                int c0 = warpX * 32 + nt * 8 + g;
                bh[nt][0] = Bh[(kb + tig) * 136 + c0];
                bh[nt][1] = Bh[(kb + tig + 4) * 136 + c0];
                bl[nt][0] = Bl[(kb + tig) * 136 + c0];
                bl[nt][1] = Bl[(kb + tig + 4) * 136 + c0];
            }
#pragma unroll
            for (int mt = 0; mt < 4; mt++) {
                int r0 = warpY * 64 + mt * 16;
                int i0 = (r0 + g) * 36 + kb + tig;
                int i1 = i0 + 8 * 36;
                uint32_t a0 = Ah[i0],     a1 = Ah[i1];
                uint32_t a2 = Ah[i0 + 4], a3 = Ah[i1 + 4];
                uint32_t l0 = Al[i0],     l1 = Al[i1];
                uint32_t l2 = Al[i0 + 4], l3 = Al[i1 + 4];
#pragma unroll
                for (int nt = 0; nt < 4; nt++) {
                    MMA_TF32(acc[mt][nt], a0, a1, a2, a3, bh[nt][0], bh[nt][1]);
                    MMA_TF32(acc[mt][nt], a0, a1, a2, a3, bl[nt][0], bl[nt][1]);
                    MMA_TF32(acc[mt][nt], l0, l1, l2, l3, bh[nt][0], bh[nt][1]);
                }
            }
        }
        __syncthreads();
    }

    // writeout to gmem (same acc->(row,col) mapping as kernel A, float2 stores)
#pragma unroll
    for (int mt = 0; mt < 4; mt++) {
        int r = rowBase + warpY * 64 + mt * 16 + g;
#pragma unroll
        for (int nt = 0; nt < 4; nt++) {
            int c = colBase + warpX * 32 + nt * 8 + tig * 2;
            float2 f0; f0.x = acc[mt][nt][0]; f0.y = acc[mt][nt][1];
            float2 f1; f1.x = acc[mt][nt][2]; f1.y = acc[mt][nt][3];
            *(float2*)&C[(size_t)r * 512 + c]       = f0;
            *(float2*)&C[(size_t)(r + 8) * 512 + c] = f1;
        }
    }
}

// ============================================================================
// Kernel C2 (R13 geometry): per 32-token block — splat all heads in-place +
// out = y @ Wo written back to the SAME rows of d_out. 128 blocks, 136 KB smem.
// ============================================================================
__global__ __launch_bounds__(256) void splat_out_kernel(
    float* __restrict__ io, const float* __restrict__ Wo,
    const float* __restrict__ lscale, const float* __restrict__ pos,
    const float* __restrict__ amp)
{
    if (Wo == nullptr) return;   // warm-up guard
    extern __shared__ float sm[];
    float* qs   = sm;               // [32][512]
    float* Ws   = sm + 16384;       // [32][512]
    float* sp   = Ws + 16384;
    float* sM   = sp + 1024;
    float* sinv = sM + 1024;
    float* samp = sinv + 16;
    float* sss  = samp + 16;

    const int tid = threadIdx.x;
    const int tokBase = blockIdx.x * 32;
    const int b = tokBase >> 11;
    const int warp = tid >> 5, lane = tid & 31;
    const int tg = tid >> 6, cg = tid & 63;

#pragma unroll
    for (int i = 0; i < 16; i++) {
        int f = tid + i * 256;
        int r = f >> 7, c4 = f & 127;
        *(float4*)&qs[r * 512 + c4 * 4] = *(const float4*)&io[(size_t)(tokBase + r) * Dq + c4 * 4];
    }
    __syncthreads();

    for (int h = 0; h < Hq; h++) {
        {
            int r = tid >> 4, c4 = tid & 15;
            *(float4*)&sp[r * 64 + c4 * 4] = *(const float4*)&pos[(h * Kq + r) * DHq + c4 * 4];
            *(float4*)&sM[r * 64 + c4 * 4] = *(const float4*)&g_M[((size_t)(b * 8 + h) * Kq + r) * DHq + c4 * 4];
        }
        if (tid < Kq) {
            float sc = __expf(lscale[h * Kq + tid]);
            sc = fminf(fmaxf(sc, 0.1f), 2.0f);
            sinv[tid] = 1.0f / (2.0f * sc * sc);
            samp[tid] = amp[h * Kq + tid];
            sss[tid]  = g_ss[(b * 8 + h) * Kq + tid];
        }
        __syncthreads();
#pragma unroll
        for (int i = 0; i < 4; i++) {
            int tok = warp * 4 + i;
            float q0 = qs[tok * 512 + h * 64 + lane];
            float q1 = qs[tok * 512 + h * 64 + lane + 32];
            float den = 0.f, y0 = 0.f, y1 = 0.f;
#pragma unroll
            for (int k = 0; k < Kq; k++) {
                float d0 = q0 - sp[k * 64 + lane];
                float d1 = q1 - sp[k * 64 + lane + 32];
                float dd = warpSum(d0 * d0 + d1 * d1);
                float w  = __expf(-dd * sinv[k]) * samp[k];
                den = fmaf(w, sss[k], den);
                y0  = fmaf(w, sM[k * 64 + lane],      y0);
                y1  = fmaf(w, sM[k * 64 + lane + 32], y1);
            }
            float r = 1.0f / (den + EPSq);
            qs[tok * 512 + h * 64 + lane]      = y0 * r;
            qs[tok * 512 + h * 64 + lane + 32] = y1 * r;
        }
        __syncthreads();
    }

#define DECLO(p) u64t o##p##0 = 0, o##p##1 = 0, o##p##2 = 0, o##p##3 = 0, \
                      o##p##4 = 0, o##p##5 = 0, o##p##6 = 0, o##p##7 = 0;
    DECLO(0) DECLO(1) DECLO(2) DECLO(3)
#undef DECLO

    for (int k0 = 0; k0 < Dq; k0 += 32) {
#pragma unroll
        for (int i = 0; i < 16; i++) {
            int f = tid + i * 256;
            int r = f >> 7, c4 = f & 127;
            *(float4*)&Ws[r * 512 + c4 * 4] = *(const float4*)&Wo[(size_t)(k0 + r) * Dq + c4 * 4];
        }
        __syncthreads();
#pragma unroll 2
        for (int kk = 0; kk < 32; kk++) {
            u64t wp0 = packrep(Ws[kk * 512 + cg]);
            u64t wp1 = packrep(Ws[kk * 512 + cg + 64]);
            u64t wp2 = packrep(Ws[kk * 512 + cg + 128]);
            u64t wp3 = packrep(Ws[kk * 512 + cg + 192]);
            u64t wp4 = packrep(Ws[kk * 512 + cg + 256]);
            u64t wp5 = packrep(Ws[kk * 512 + cg + 320]);
            u64t wp6 = packrep(Ws[kk * 512 + cg + 384]);
            u64t wp7 = packrep(Ws[kk * 512 + cg + 448]);
            u64t yp0 = pack2(qs[(tg * 8 + 0) * 512 + k0 + kk], qs[(tg * 8 + 1) * 512 + k0 + kk]);
            u64t yp1 = pack2(qs[(tg * 8 + 2) * 512 + k0 + kk], qs[(tg * 8 + 3) * 512 + k0 + kk]);
            u64t yp2 = pack2(qs[(tg * 8 + 4) * 512 + k0 + kk], qs[(tg * 8 + 5) * 512 + k0 + kk]);
            u64t yp3 = pack2(qs[(tg * 8 + 6) * 512 + k0 + kk], qs[(tg * 8 + 7) * 512 + k0 + kk]);
#define C2FMA(p, yp) { fma2(o##p##0, yp, wp0); fma2(o##p##1, yp, wp1); fma2(o##p##2, yp, wp2); fma2(o##p##3, yp, wp3); \
                       fma2(o##p##4, yp, wp4); fma2(o##p##5, yp, wp5); fma2(o##p##6, yp, wp6); fma2(o##p##7, yp, wp7); }
            C2FMA(0, yp0) C2FMA(1, yp1) C2FMA(2, yp2) C2FMA(3, yp3)
#undef C2FMA
        }
        __syncthreads();
    }

#define C2OUT(p) { \
    float* r0 = &io[(size_t)(tokBase + tg * 8 + 2 * (p)) * Dq + cg]; \
    float* r1 = r0 + Dq; float2 f; \
    f = unpk(o##p##0); r0[0]   = f.x; r1[0]   = f.y; \
    f = unpk(o##p##1); r0[64]  = f.x; r1[64]  = f.y; \
    f = unpk(o##p##2); r0[128] = f.x; r1[128] = f.y; \
    f = unpk(o##p##3); r0[192] = f.x; r1[192] = f.y; \
    f = unpk(o##p##4); r0[256] = f.x; r1[256] = f.y; \
    f = unpk(o##p##5); r0[320] = f.x; r1[320] = f.y; \
    f = unpk(o##p##6); r0[384] = f.x; r1[384] = f.y; \
    f = unpk(o##p##7); r0[448] = f.x; r1[448] = f.y; }
    C2OUT(0) C2OUT(1) C2OUT(2) C2OUT(3)
#undef C2OUT
}

// ---------------- static-init warm-up + stream/event creation ----------------
namespace {
cudaStream_t g_side[16] = {};
cudaEvent_t  g_evF[16]  = {};
cudaEvent_t  g_evJ[16]  = {};

void warm_one_device() {
    (void)cudaFree(0);
    void* p = nullptr;
    (void)cudaGetSymbolAddress(&p, g_M);
    (void)cudaGetSymbolAddress(&p, g_Mpart);
    (void)cudaFuncSetAttribute(kv_splat_kernel,
            cudaFuncAttributeMaxDynamicSharedMemorySize, A_SMEM_BYTES);
    (void)cudaFuncSetAttribute(q_proj_kernel,
            cudaFuncAttributeMaxDynamicSharedMemorySize, C1_SMEM_BYTES);
    (void)cudaFuncSetAttribute(splat_out_kernel,
            cudaFuncAttributeMaxDynamicSharedMemorySize, C2_SMEM_BYTES);
    {
        dim3 grid(ACH, Hq);
        kv_splat_kernel<<<grid, 256, A_SMEM_BYTES>>>(nullptr, nullptr, nullptr, nullptr, nullptr);
    }
    reduce_kernel<<<64, 256>>>(0);
    {
        dim3 grid(4, 32);
        q_proj_kernel<<<grid, 256, C1_SMEM_BYTES>>>(nullptr, nullptr, nullptr);
    }
    splat_out_kernel<<<128, 256, C2_SMEM_BYTES>>>(nullptr, nullptr, nullptr, nullptr, nullptr);
    (void)cudaDeviceSynchronize();
    int d = 0;
    if (cudaGetDevice(&d) == cudaSuccess && d >= 0 && d < 16 && g_side[d] == nullptr) {
        if (cudaStreamCreateWithFlags(&g_side[d], cudaStreamNonBlocking) != cudaSuccess)
            g_side[d] = nullptr;
        if (g_side[d]) {
            if (cudaEventCreateWithFlags(&g_evF[d], cudaEventDisableTiming) != cudaSuccess) g_evF[d] = nullptr;
            if (cudaEventCreateWithFlags(&g_evJ[d], cudaEventDisableTiming) != cudaSuccess) g_evJ[d] = nullptr;
        }
    }
    (void)cudaGetLastError();
}
struct ModuleWarmup {
    ModuleWarmup() {
        int prev = 0;
        (void)cudaGetDevice(&prev);
        int n = 0;
        if (cudaGetDeviceCount(&n) != cudaSuccess) n = 0;
        for (int d = 0; d < n && d < 16; d++) {
            if (cudaSetDevice(d) != cudaSuccess) continue;
            warm_one_device();
        }
        (void)cudaSetDevice(prev);
        (void)cudaGetLastError();
    }
};
ModuleWarmup s_warmup;
}

// ---------------- launch ----------------
extern "C" void kernel_launch(void* const* d_in, const int* in_sizes, int n_in,
                              void* d_out, int out_size)
{
    const float* x      = (const float*)d_in[0];
    const float* Wqm    = (const float*)d_in[1];
    const float* Wkm    = (const float*)d_in[2];
    const float* Wvm    = (const float*)d_in[3];
    const float* Wom    = (const float*)d_in[4];
    const float* pos    = (const float*)d_in[5];
    const float* lscale = (const float*)d_in[6];
    const float* amp    = (const float*)d_in[7];
    float* out = (float*)d_out;

    (void)cudaFuncSetAttribute(kv_splat_kernel,
            cudaFuncAttributeMaxDynamicSharedMemorySize, A_SMEM_BYTES);
    (void)cudaFuncSetAttribute(q_proj_kernel,
            cudaFuncAttributeMaxDynamicSharedMemorySize, C1_SMEM_BYTES);
    (void)cudaFuncSetAttribute(splat_out_kernel,
            cudaFuncAttributeMaxDynamicSharedMemorySize, C2_SMEM_BYTES);

    int dev = 0;
    (void)cudaGetDevice(&dev);
    cudaStream_t side = (dev >= 0 && dev < 16) ? g_side[dev] : nullptr;
    cudaEvent_t evF = (dev >= 0 && dev < 16) ? g_evF[dev] : nullptr;
    cudaEvent_t evJ = (dev >= 0 && dev < 16) ? g_evJ[dev] : nullptr;
    const bool overlap = (side != nullptr) && (evF != nullptr) && (evJ != nullptr);

    if (overlap) {
        // fork: C1 on side stream, concurrent with A + reduce on main stream
        cudaEventRecord(evF, 0);
        cudaStreamWaitEvent(side, evF, 0);
        {
            dim3 grid(4, 32);
            q_proj_kernel<<<grid, 256, C1_SMEM_BYTES, side>>>(x, Wqm, out);
        }
        cudaEventRecord(evJ, side);
    }

    {   // K/V projection (tf32 MMA) + splat moments
        dim3 grid(ACH, Hq);
        kv_splat_kernel<<<grid, 256, A_SMEM_BYTES>>>(x, Wkm, Wvm, lscale, pos);
    }
    reduce_kernel<<<64, 256>>>(1);

    if (overlap) {
        cudaStreamWaitEvent(0, evJ, 0);   // join C1 into main stream
    } else {
        dim3 grid(4, 32);
        q_proj_kernel<<<grid, 256, C1_SMEM_BYTES>>>(x, Wqm, out);
    }

    // splat attention + output projection, in-place on d_out rows
    splat_out_kernel<<<128, 256, C2_SMEM_BYTES>>>(out, Wom, lscale, pos, amp);
}

// round 17
// speedup vs baseline: 1.4803x; 1.2331x over previous
#include <cuda_runtime.h>
#include <math.h>
#include <stdint.h>

// Problem constants
#define Bq   2
#define Sq   2048
#define Dq   512
#define Hq   8
#define Kq   16
#define DHq  64
#define EPSq 1e-8f
#define BS   4096
#define BH   16
#define ACH  32     // kv token chunks of 128 (16 per batch)

// ---------------- tiny device scratch (~1.6 MB total) ----------------
__device__ float g_Mpart[ACH * Hq * Kq * DHq];  // 1 MB
__device__ float g_sspart[ACH * Hq * Kq];       // 16 KB
__device__ float g_M[BH * Kq * DHq];            // 64 KB
__device__ float g_ss[BH * Kq];                 // 1 KB
__device__ float g_P[Bq * 128 * Dq];            // 512 KB  P[b][h*16+k][c]

__device__ __forceinline__ float warpSum(float p) {
    p += __shfl_xor_sync(0xffffffffu, p, 16);
    p += __shfl_xor_sync(0xffffffffu, p, 8);
    p += __shfl_xor_sync(0xffffffffu, p, 4);
    p += __shfl_xor_sync(0xffffffffu, p, 2);
    p += __shfl_xor_sync(0xffffffffu, p, 1);
    return p;
}

// ---------------- packed f32x2 helpers ----------------
typedef unsigned long long u64t;
__device__ __forceinline__ u64t pack2(float lo, float hi) {
    u64t r; asm("mov.b64 %0, {%1, %2};" : "=l"(r) : "f"(lo), "f"(hi)); return r;
}
__device__ __forceinline__ u64t packrep(float v) { return pack2(v, v); }
__device__ __forceinline__ void fma2(u64t& c, u64t a, u64t b) {
    asm("fma.rn.f32x2 %0, %1, %2, %0;" : "+l"(c) : "l"(a), "l"(b));
}
__device__ __forceinline__ float2 unpk(u64t v) {
    float2 f; asm("mov.b64 {%0, %1}, %2;" : "=f"(f.x), "=f"(f.y) : "l"(v)); return f;
}

// ---------------- tf32 split helpers ----------------
__device__ __forceinline__ void cvt_split(float v, uint32_t& h, uint32_t& l) {
    asm("cvt.rna.tf32.f32 %0, %1;" : "=r"(h) : "f"(v));
    float hf = __uint_as_float(h);
    float lo = v - hf;                      // exact residual
    asm("cvt.rna.tf32.f32 %0, %1;" : "=r"(l) : "f"(lo));
}

#define MMA_TF32(c, a0_, a1_, a2_, a3_, b0_, b1_) \
    asm volatile("mma.sync.aligned.m16n8k8.row.col.f32.tf32.tf32.f32 " \
                 "{%0,%1,%2,%3}, {%4,%5,%6,%7}, {%8,%9}, {%0,%1,%2,%3};" \
                 : "+f"((c)[0]), "+f"((c)[1]), "+f"((c)[2]), "+f"((c)[3]) \
                 : "r"(a0_), "r"(a1_), "r"(a2_), "r"(a3_), \
                   "r"(b0_), "r"(b1_))

// smem plans
#define A_SMEM_FLOATS (17920 + 1040 + 16)
#define A_SMEM_BYTES  (A_SMEM_FLOATS * 4)                       // 75904
#define C1_SMEM_FLOATS 17920
#define C1_SMEM_BYTES  (C1_SMEM_FLOATS * 4)                     // 71680
// C2: ws[32][128]=4096, buf[32][512]=16384 (q then P chunks), sp 1024, consts 48
#define C2_SMEM_FLOATS (4096 + 16384 + 1024 + 48)
#define C2_SMEM_BYTES  (C2_SMEM_FLOATS * 4)                     // 86208

// ============================================================================
// Kernel A: fused K/V projection via tf32 MMA (3-term split) + splat moments.
// ============================================================================
__global__ __launch_bounds__(256, 2) void kv_splat_kernel(
    const float* __restrict__ x,  const float* __restrict__ Wk,
    const float* __restrict__ Wv, const float* __restrict__ lscale,
    const float* __restrict__ pos)
{
    if (x == nullptr) return;   // warm-up guard
    extern __shared__ float sm[];
    uint32_t* Ah = (uint32_t*)sm;            // [128][36]
    uint32_t* Al = Ah + 4608;
    uint32_t* Bh = Ah + 9216;                // [32][136]
    uint32_t* Bl = Ah + 13568;               // ends at 17920
    float* ks   = sm;                        // OVERLAY: [128][68]
    float* vs   = sm + 8704;
    float* sp   = sm + 17920;                // [16][65]
    float* sinv = sm + 18960;                // [16]

    const int chunk = blockIdx.x;
    const int h     = blockIdx.y;
    const int rowBase = chunk * 128;
    const int tid  = threadIdx.x;
    const int lane = tid & 31, warp = tid >> 5;
    const int warpY = warp >> 2;
    const int warpX = warp & 3;
    const int g = lane >> 2, tig = lane & 3;

#pragma unroll
    for (int i = 0; i < 4; i++) {
        int idx = tid + i * 256;
        int r = idx >> 6, d = idx & 63;
        sp[r * 65 + d] = pos[h * 1024 + r * 64 + d];
    }
    if (tid < 16) {
        float sc = __expf(lscale[h * 16 + tid]);
        sc = fminf(fmaxf(sc, 0.1f), 2.0f);
        sinv[tid] = 1.0f / (2.0f * sc * sc);
    }

    float acc[4][4][4];
#pragma unroll
    for (int mt = 0; mt < 4; mt++)
#pragma unroll
        for (int nt = 0; nt < 4; nt++)
#pragma unroll
            for (int j = 0; j < 4; j++) acc[mt][nt][j] = 0.0f;

    for (int kc = 0; kc < 512; kc += 32) {
#pragma unroll
        for (int i = 0; i < 16; i++) {
            int idx = tid + i * 256;
            int row = idx >> 5, kk = idx & 31;
            float v = x[(size_t)(rowBase + row) * 512 + kc + kk];
            uint32_t hb, lb; cvt_split(v, hb, lb);
            Ah[row * 36 + kk] = hb;
            Al[row * 36 + kk] = lb;
        }
#pragma unroll
        for (int i = 0; i < 16; i++) {
            int idx = tid + i * 256;
            int kk = idx >> 7, col = idx & 127;
            float v = (col < 64)
                ? Wk[(size_t)(kc + kk) * 512 + h * 64 + col]
                : Wv[(size_t)(kc + kk) * 512 + h * 64 + col - 64];
            uint32_t hb, lb; cvt_split(v, hb, lb);
            Bh[kk * 136 + col] = hb;
            Bl[kk * 136 + col] = lb;
        }
        __syncthreads();

#pragma unroll
        for (int s8 = 0; s8 < 4; s8++) {
            const int kb = s8 * 8;
            uint32_t bh[4][2], bl[4][2];
#pragma unroll
            for (int nt = 0; nt < 4; nt++) {
                int c0 = warpX * 32 + nt * 8 + g;
                bh[nt][0] = Bh[(kb + tig) * 136 + c0];
                bh[nt][1] = Bh[(kb + tig + 4) * 136 + c0];
                bl[nt][0] = Bl[(kb + tig) * 136 + c0];
                bl[nt][1] = Bl[(kb + tig + 4) * 136 + c0];
            }
#pragma unroll
            for (int mt = 0; mt < 4; mt++) {
                int r0 = warpY * 64 + mt * 16;
                int i0 = (r0 + g) * 36 + kb + tig;
                int i1 = i0 + 8 * 36;
                uint32_t a0 = Ah[i0],     a1 = Ah[i1];
                uint32_t a2 = Ah[i0 + 4], a3 = Ah[i1 + 4];
                uint32_t l0 = Al[i0],     l1 = Al[i1];
                uint32_t l2 = Al[i0 + 4], l3 = Al[i1 + 4];
#pragma unroll
                for (int nt = 0; nt < 4; nt++) {
                    MMA_TF32(acc[mt][nt], a0, a1, a2, a3, bh[nt][0], bh[nt][1]);
                    MMA_TF32(acc[mt][nt], a0, a1, a2, a3, bl[nt][0], bl[nt][1]);
                    MMA_TF32(acc[mt][nt], l0, l1, l2, l3, bh[nt][0], bh[nt][1]);
                }
            }
        }
        __syncthreads();
    }

    {
        float* cb = (warpX < 2) ? ks : vs;
#pragma unroll
        for (int mt = 0; mt < 4; mt++) {
            int r = warpY * 64 + mt * 16 + g;
#pragma unroll
            for (int nt = 0; nt < 4; nt++) {
                int c = (warpX & 1) * 32 + nt * 8 + tig * 2;
                cb[r * 68 + c]           = acc[mt][nt][0];
                cb[r * 68 + c + 1]       = acc[mt][nt][1];
                cb[(r + 8) * 68 + c]     = acc[mt][nt][2];
                cb[(r + 8) * 68 + c + 1] = acc[mt][nt][3];
            }
        }
    }
    __syncthreads();

    const float p0a = sp[warp * 65 + lane],       p1a = sp[warp * 65 + lane + 32];
    const float p0b = sp[(warp + 8) * 65 + lane], p1b = sp[(warp + 8) * 65 + lane + 32];
    const float inva = sinv[warp], invb = sinv[warp + 8];

    float mA0 = 0.f, mA1 = 0.f, sA = 0.f;
    float mB0 = 0.f, mB1 = 0.f, sB = 0.f;
#pragma unroll 2
    for (int tt = 0; tt < 128; tt++) {
        float k0v = ks[tt * 68 + lane], k1v = ks[tt * 68 + lane + 32];
        float v0  = vs[tt * 68 + lane], v1  = vs[tt * 68 + lane + 32];
        float d0 = k0v - p0a, d1 = k1v - p1a;
        float dd = warpSum(d0 * d0 + d1 * d1);
        float af = __expf(-dd * inva);
        mA0 = fmaf(af, v0, mA0); mA1 = fmaf(af, v1, mA1); sA += af;
        d0 = k0v - p0b; d1 = k1v - p1b;
        dd = warpSum(d0 * d0 + d1 * d1);
        af = __expf(-dd * invb);
        mB0 = fmaf(af, v0, mB0); mB1 = fmaf(af, v1, mB1); sB += af;
    }
    const size_t base = ((size_t)chunk * Hq + h) * Kq;
    float* Mp  = &g_Mpart[(base + warp) * DHq];
    Mp[lane] = mA0; Mp[lane + 32] = mA1;
    float* Mp2 = &g_Mpart[(base + warp + 8) * DHq];
    Mp2[lane] = mB0; Mp2[lane + 32] = mB1;
    if (lane == 0) {
        g_sspart[base + warp]     = sA;
        g_sspart[base + warp + 8] = sB;
    }
}

// ============================================================================
// Kernel B: fixed-order reduction of chunk partials (deterministic).
// ============================================================================
__global__ __launch_bounds__(256) void reduce_kernel(int real)
{
    if (!real) return;   // warm-up guard
    const int i = blockIdx.x * 256 + threadIdx.x;
    if (i < BH * Kq * DHq) {
        int bh = i >> 10;
        int b = bh >> 3, h = bh & 7;
        int rest = i & 1023;
        float a = 0.f;
#pragma unroll
        for (int c = 0; c < 16; c++)
            a += g_Mpart[(((size_t)(b * 16 + c) * Hq + h) << 10) + rest];
        g_M[i] = a;
    }
    if (i < BH * Kq) {
        int bh = i >> 4;
        int b = bh >> 3, h = bh & 7;
        int k = i & 15;
        float a = 0.f;
#pragma unroll
        for (int c = 0; c < 16; c++)
            a += g_sspart[((size_t)(b * 16 + c) * Hq + h) * Kq + k];
        g_ss[i] = a;
    }
}

// ============================================================================
// Kernel P: P[b][h*16+k][c] = sum_d M[b,h,k,d] * Wo[h*64+d][c].
// grid (4 col-chunks, BH=16), 256 threads. Tiny (0.017 GFLOP total).
// ============================================================================
__global__ __launch_bounds__(256) void p_kernel(const float* __restrict__ Wo)
{
    if (Wo == nullptr) return;   // warm-up guard
    __shared__ float sM[Kq * DHq];      // 1024 floats

    const int bh = blockIdx.y;
    const int b = bh >> 3, h = bh & 7;
    const int colBase = blockIdx.x * 128;
    const int tid = threadIdx.x;

    {   // load M rows for this (b,h)
        int r = tid >> 4, c4 = tid & 15;
        *(float4*)&sM[r * 64 + c4 * 4] = *(const float4*)&g_M[((size_t)bh * Kq + r) * DHq + c4 * 4];
    }
    __syncthreads();

    const int c  = colBase + (tid & 127);
    const int k0 = (tid >> 7) * 8;      // rows k0..k0+7

    float a0 = 0.f, a1 = 0.f, a2 = 0.f, a3 = 0.f;
    float a4 = 0.f, a5 = 0.f, a6 = 0.f, a7 = 0.f;
#pragma unroll 4
    for (int d = 0; d < 64; d++) {
        float wv = Wo[(size_t)(h * 64 + d) * 512 + c];
        a0 = fmaf(sM[(k0 + 0) * 64 + d], wv, a0);
        a1 = fmaf(sM[(k0 + 1) * 64 + d], wv, a1);
        a2 = fmaf(sM[(k0 + 2) * 64 + d], wv, a2);
        a3 = fmaf(sM[(k0 + 3) * 64 + d], wv, a3);
        a4 = fmaf(sM[(k0 + 4) * 64 + d], wv, a4);
        a5 = fmaf(sM[(k0 + 5) * 64 + d], wv, a5);
        a6 = fmaf(sM[(k0 + 6) * 64 + d], wv, a6);
        a7 = fmaf(sM[(k0 + 7) * 64 + d], wv, a7);
    }
    const size_t pb = (size_t)(b * 128 + h * 16 + k0) * 512 + c;
    g_P[pb + 0 * 512] = a0; g_P[pb + 1 * 512] = a1;
    g_P[pb + 2 * 512] = a2; g_P[pb + 3 * 512] = a3;
    g_P[pb + 4 * 512] = a4; g_P[pb + 5 * 512] = a5;
    g_P[pb + 6 * 512] = a6; g_P[pb + 7 * 512] = a7;
}

// ============================================================================
// Kernel C1: q = x @ Wq via tf32 MMA -> d_out staging (validated machinery).
// ============================================================================
__global__ __launch_bounds__(256, 2) void q_proj_kernel(
    const float* __restrict__ x, const float* __restrict__ Wq, float* __restrict__ C)
{
    if (x == nullptr) return;   // warm-up guard
    extern __shared__ float sm[];
    uint32_t* Ah = (uint32_t*)sm;
    uint32_t* Al = Ah + 4608;
    uint32_t* Bh = Ah + 9216;
    uint32_t* Bl = Ah + 13568;

    const int rowBase = blockIdx.y * 128;
    const int colBase = blockIdx.x * 128;
    const int tid  = threadIdx.x;
    const int lane = tid & 31, warp = tid >> 5;
    const int warpY = warp >> 2;
    const int warpX = warp & 3;
    const int g = lane >> 2, tig = lane & 3;

    float acc[4][4][4];
#pragma unroll
    for (int mt = 0; mt < 4; mt++)
#pragma unroll
        for (int nt = 0; nt < 4; nt++)
#pragma unroll
            for (int j = 0; j < 4; j++) acc[mt][nt][j] = 0.0f;

    for (int kc = 0; kc < 512; kc += 32) {
#pragma unroll
        for (int i = 0; i < 16; i++) {
            int idx = tid + i * 256;
            int row = idx >> 5, kk = idx & 31;
            float v = x[(size_t)(rowBase + row) * 512 + kc + kk];
            uint32_t hb, lb; cvt_split(v, hb, lb);
            Ah[row * 36 + kk] = hb;
            Al[row * 36 + kk] = lb;
        }
#pragma unroll
        for (int i = 0; i < 16; i++) {
            int idx = tid + i * 256;
            int kk = idx >> 7, col = idx & 127;
            float v = Wq[(size_t)(kc + kk) * 512 + colBase + col];
            uint32_t hb, lb; cvt_split(v, hb, lb);
            Bh[kk * 136 + col] = hb;
            Bl[kk * 136 + col] = lb;
        }
        __syncthreads();

#pragma unroll
        for (int s8 = 0; s8 < 4; s8++) {
            const int kb = s8 * 8;
            uint32_t bh[4][2], bl[4][2];
#pragma unroll
            for (int nt = 0; nt < 4; nt++) {
                int c0 = warpX * 32 + nt * 8 + g;
                bh[nt][0] = Bh[(kb + tig) * 136 + c0];
                bh[nt][1] = Bh[(kb + tig + 4) * 136 + c0];
                bl[nt][0] = Bl[(kb + tig) * 136 + c0];
                bl[nt][1] = Bl[(kb + tig + 4) * 136 + c0];
            }
#pragma unroll
            for (int mt = 0; mt < 4; mt++) {
                int r0 = warpY * 64 + mt * 16;
                int i0 = (r0 + g) * 36 + kb + tig;
                int i1 = i0 + 8 * 36;
                uint32_t a0 = Ah[i0],     a1 = Ah[i1];
                uint32_t a2 = Ah[i0 + 4], a3 = Ah[i1 + 4];
                uint32_t l0 = Al[i0],     l1 = Al[i1];
                uint32_t l2 = Al[i0 + 4], l3 = Al[i1 + 4];
#pragma unroll
                for (int nt = 0; nt < 4; nt++) {
                    MMA_TF32(acc[mt][nt], a0, a1, a2, a3, bh[nt][0], bh[nt][1]);
                    MMA_TF32(acc[mt][nt], a0, a1, a2, a3, bl[nt][0], bl[nt][1]);
                    MMA_TF32(acc[mt][nt], l0, l1, l2, l3, bh[nt][0], bh[nt][1]);
                }
            }
        }
        __syncthreads();
    }

#pragma unroll
    for (int mt = 0; mt < 4; mt++) {
        int r = rowBase + warpY * 64 + mt * 16 + g;
#pragma unroll
        for (int nt = 0; nt < 4; nt++) {
            int c = colBase + warpX * 32 + nt * 8 + tig * 2;
            float2 f0; f0.x = acc[mt][nt][0]; f0.y = acc[mt][nt][1];
            float2 f1; f1.x = acc[mt][nt][2]; f1.y = acc[mt][nt][3];
            *(float2*)&C[(size_t)r * 512 + c]       = f0;
            *(float2*)&C[(size_t)(r + 8) * 512 + c] = f1;
        }
    }
}

// ============================================================================
// Kernel C2: per 32-token block — splat weights ws[32][128], then
// out = ws @ P_b[128][512] written in-place to the same d_out rows.
// 128 blocks x 256 threads, 84 KB smem -> 2 blocks/SM.
// ============================================================================
__global__ __launch_bounds__(256, 2) void splat_out_kernel(
    float* __restrict__ io, const float* __restrict__ lscale,
    const float* __restrict__ pos, const float* __restrict__ amp)
{
    if (lscale == nullptr) return;   // warm-up guard
    extern __shared__ float sm[];
    float* ws   = sm;               // [32][128]
    float* buf  = sm + 4096;        // [32][512]: q, then P chunks
    float* sp   = sm + 4096 + 16384;// [16][64]
    float* sinv = sp + 1024;
    float* samp = sinv + 16;
    float* sss  = samp + 16;

    const int tid = threadIdx.x;
    const int tokBase = blockIdx.x * 32;
    const int b = tokBase >> 11;
    const int warp = tid >> 5, lane = tid & 31;
    const int tg = tid >> 6, cg = tid & 63;

    // load q tile [32][512]
#pragma unroll
    for (int i = 0; i < 16; i++) {
        int f = tid + i * 256;
        int r = f >> 7, c4 = f & 127;
        *(float4*)&buf[r * 512 + c4 * 4] = *(const float4*)&io[(size_t)(tokBase + r) * Dq + c4 * 4];
    }
    __syncthreads();

    // splat: compute normalized weights ws[tok][h*16+k]
    for (int h = 0; h < Hq; h++) {
        {
            int r = tid >> 4, c4 = tid & 15;
            *(float4*)&sp[r * 64 + c4 * 4] = *(const float4*)&pos[(h * Kq + r) * DHq + c4 * 4];
        }
        if (tid < Kq) {
            float sc = __expf(lscale[h * Kq + tid]);
            sc = fminf(fmaxf(sc, 0.1f), 2.0f);
            sinv[tid] = 1.0f / (2.0f * sc * sc);
            samp[tid] = amp[h * Kq + tid];
            sss[tid]  = g_ss[(b * 8 + h) * Kq + tid];
        }
        __syncthreads();
#pragma unroll
        for (int i = 0; i < 4; i++) {
            int tok = warp * 4 + i;
            float q0 = buf[tok * 512 + h * 64 + lane];
            float q1 = buf[tok * 512 + h * 64 + lane + 32];
            float den = 0.f, wkeep = 0.f;
#pragma unroll
            for (int k = 0; k < Kq; k++) {
                float d0 = q0 - sp[k * 64 + lane];
                float d1 = q1 - sp[k * 64 + lane + 32];
                float dd = warpSum(d0 * d0 + d1 * d1);
                float w  = __expf(-dd * sinv[k]) * samp[k];   // same on all lanes
                den = fmaf(w, sss[k], den);
                if (lane == k) wkeep = w;                      // lane k keeps w_k
            }
            float r = 1.0f / (den + EPSq);
            if (lane < Kq)
                ws[tok * 128 + h * 16 + lane] = wkeep * r;
        }
        __syncthreads();
    }

    // contraction: out[32][512] = ws[32][128] @ P_b[128][512]
#define DECLO(p) u64t o##p##0 = 0, o##p##1 = 0, o##p##2 = 0, o##p##3 = 0, \
                      o##p##4 = 0, o##p##5 = 0, o##p##6 = 0, o##p##7 = 0;
    DECLO(0) DECLO(1) DECLO(2) DECLO(3)
#undef DECLO

    const float* Pb = &g_P[(size_t)b * 128 * 512];
    for (int pc = 0; pc < 128; pc += 32) {
        __syncthreads();   // all reads of previous buf contents done
#pragma unroll
        for (int i = 0; i < 16; i++) {
            int f = tid + i * 256;
            int r = f >> 7, c4 = f & 127;
            *(float4*)&buf[r * 512 + c4 * 4] = *(const float4*)&Pb[(size_t)(pc + r) * 512 + c4 * 4];
        }
        __syncthreads();
#pragma unroll 2
        for (int kk = 0; kk < 32; kk++) {
            u64t wp0 = packrep(buf[kk * 512 + cg]);
            u64t wp1 = packrep(buf[kk * 512 + cg + 64]);
            u64t wp2 = packrep(buf[kk * 512 + cg + 128]);
            u64t wp3 = packrep(buf[kk * 512 + cg + 192]);
            u64t wp4 = packrep(buf[kk * 512 + cg + 256]);
            u64t wp5 = packrep(buf[kk * 512 + cg + 320]);
            u64t wp6 = packrep(buf[kk * 512 + cg + 384]);
            u64t wp7 = packrep(buf[kk * 512 + cg + 448]);
            u64t yp0 = pack2(ws[(tg * 8 + 0) * 128 + pc + kk], ws[(tg * 8 + 1) * 128 + pc + kk]);
            u64t yp1 = pack2(ws[(tg * 8 + 2) * 128 + pc + kk], ws[(tg * 8 + 3) * 128 + pc + kk]);
            u64t yp2 = pack2(ws[(tg * 8 + 4) * 128 + pc + kk], ws[(tg * 8 + 5) * 128 + pc + kk]);
            u64t yp3 = pack2(ws[(tg * 8 + 6) * 128 + pc + kk], ws[(tg * 8 + 7) * 128 + pc + kk]);
#define C2FMA(p, yp) { fma2(o##p##0, yp, wp0); fma2(o##p##1, yp, wp1); fma2(o##p##2, yp, wp2); fma2(o##p##3, yp, wp3); \
                       fma2(o##p##4, yp, wp4); fma2(o##p##5, yp, wp5); fma2(o##p##6, yp, wp6); fma2(o##p##7, yp, wp7); }
            C2FMA(0, yp0) C2FMA(1, yp1) C2FMA(2, yp2) C2FMA(3, yp3)
#undef C2FMA
        }
    }

#define C2OUT(p) { \
    float* r0 = &io[(size_t)(tokBase + tg * 8 + 2 * (p)) * Dq + cg]; \
    float* r1 = r0 + Dq; float2 f; \
    f = unpk(o##p##0); r0[0]   = f.x; r1[0]   = f.y; \
    f = unpk(o##p##1); r0[64]  = f.x; r1[64]  = f.y; \
    f = unpk(o##p##2); r0[128] = f.x; r1[128] = f.y; \
    f = unpk(o##p##3); r0[192] = f.x; r1[192] = f.y; \
    f = unpk(o##p##4); r0[256] = f.x; r1[256] = f.y; \
    f = unpk(o##p##5); r0[320] = f.x; r1[320] = f.y; \
    f = unpk(o##p##6); r0[384] = f.x; r1[384] = f.y; \
    f = unpk(o##p##7); r0[448] = f.x; r1[448] = f.y; }
    C2OUT(0) C2OUT(1) C2OUT(2) C2OUT(3)
#undef C2OUT
}

// ---------------- static-init warm-up + stream/event creation ----------------
namespace {
cudaStream_t g_side[16] = {};
cudaEvent_t  g_evF[16]  = {};
cudaEvent_t  g_evJ[16]  = {};

void warm_one_device() {
    (void)cudaFree(0);
    void* p = nullptr;
    (void)cudaGetSymbolAddress(&p, g_M);
    (void)cudaGetSymbolAddress(&p, g_Mpart);
    (void)cudaGetSymbolAddress(&p, g_P);
    (void)cudaFuncSetAttribute(kv_splat_kernel,
            cudaFuncAttributeMaxDynamicSharedMemorySize, A_SMEM_BYTES);
    (void)cudaFuncSetAttribute(q_proj_kernel,
            cudaFuncAttributeMaxDynamicSharedMemorySize, C1_SMEM_BYTES);
    (void)cudaFuncSetAttribute(splat_out_kernel,
            cudaFuncAttributeMaxDynamicSharedMemorySize, C2_SMEM_BYTES);
    {
        dim3 grid(ACH, Hq);
        kv_splat_kernel<<<grid, 256, A_SMEM_BYTES>>>(nullptr, nullptr, nullptr, nullptr, nullptr);
    }
    reduce_kernel<<<64, 256>>>(0);
    {
        dim3 grid(4, BH);
        p_kernel<<<grid, 256>>>(nullptr);
    }
    {
        dim3 grid(4, 32);
        q_proj_kernel<<<grid, 256, C1_SMEM_BYTES>>>(nullptr, nullptr, nullptr);
    }
    splat_out_kernel<<<128, 256, C2_SMEM_BYTES>>>(nullptr, nullptr, nullptr, nullptr);
    (void)cudaDeviceSynchronize();
    int d = 0;
    if (cudaGetDevice(&d) == cudaSuccess && d >= 0 && d < 16 && g_side[d] == nullptr) {
        if (cudaStreamCreateWithFlags(&g_side[d], cudaStreamNonBlocking) != cudaSuccess)
            g_side[d] = nullptr;
        if (g_side[d]) {
            if (cudaEventCreateWithFlags(&g_evF[d], cudaEventDisableTiming) != cudaSuccess) g_evF[d] = nullptr;
            if (cudaEventCreateWithFlags(&g_evJ[d], cudaEventDisableTiming) != cudaSuccess) g_evJ[d] = nullptr;
        }
    }
    (void)cudaGetLastError();
}
struct ModuleWarmup {
    ModuleWarmup() {
        int prev = 0;
        (void)cudaGetDevice(&prev);
        int n = 0;
        if (cudaGetDeviceCount(&n) != cudaSuccess) n = 0;
        for (int d = 0; d < n && d < 16; d++) {
            if (cudaSetDevice(d) != cudaSuccess) continue;
            warm_one_device();
        }
        (void)cudaSetDevice(prev);
        (void)cudaGetLastError();
    }
};
ModuleWarmup s_warmup;
}

// ---------------- launch ----------------
extern "C" void kernel_launch(void* const* d_in, const int* in_sizes, int n_in,
                              void* d_out, int out_size)
{
    const float* x      = (const float*)d_in[0];
    const float* Wqm    = (const float*)d_in[1];
    const float* Wkm    = (const float*)d_in[2];
    const float* Wvm    = (const float*)d_in[3];
    const float* Wom    = (const float*)d_in[4];
    const float* pos    = (const float*)d_in[5];
    const float* lscale = (const float*)d_in[6];
    const float* amp    = (const float*)d_in[7];
    float* out = (float*)d_out;

    (void)cudaFuncSetAttribute(kv_splat_kernel,
            cudaFuncAttributeMaxDynamicSharedMemorySize, A_SMEM_BYTES);
    (void)cudaFuncSetAttribute(q_proj_kernel,
            cudaFuncAttributeMaxDynamicSharedMemorySize, C1_SMEM_BYTES);
    (void)cudaFuncSetAttribute(splat_out_kernel,
            cudaFuncAttributeMaxDynamicSharedMemorySize, C2_SMEM_BYTES);

    int dev = 0;
    (void)cudaGetDevice(&dev);
    cudaStream_t side = (dev >= 0 && dev < 16) ? g_side[dev] : nullptr;
    cudaEvent_t evF = (dev >= 0 && dev < 16) ? g_evF[dev] : nullptr;
    cudaEvent_t evJ = (dev >= 0 && dev < 16) ? g_evJ[dev] : nullptr;
    const bool overlap = (side != nullptr) && (evF != nullptr) && (evJ != nullptr);

    if (overlap) {
        // fork: C1 on side stream, concurrent with A + reduce + P on main stream
        cudaEventRecord(evF, 0);
        cudaStreamWaitEvent(side, evF, 0);
        {
            dim3 grid(4, 32);
            q_proj_kernel<<<grid, 256, C1_SMEM_BYTES, side>>>(x, Wqm, out);
        }
        cudaEventRecord(evJ, side);
    }

    {   // K/V projection (tf32 MMA) + splat moments
        dim3 grid(ACH, Hq);
        kv_splat_kernel<<<grid, 256, A_SMEM_BYTES>>>(x, Wkm, Wvm, lscale, pos);
    }
    reduce_kernel<<<64, 256>>>(1);
    {   // P = M @ Wo (tiny)
        dim3 grid(4, BH);
        p_kernel<<<grid, 256>>>(Wom);
    }

    if (overlap) {
        cudaStreamWaitEvent(0, evJ, 0);   // join C1 into main stream
    } else {
        dim3 grid(4, 32);
        q_proj_kernel<<<grid, 256, C1_SMEM_BYTES>>>(x, Wqm, out);
    }

    // splat weights + rank-128 output contraction, in-place on d_out rows
    splat_out_kernel<<<128, 256, C2_SMEM_BYTES>>>(out, lscale, pos, amp);
}